// round 1
// baseline (speedup 1.0000x reference)
#include <cuda_runtime.h>

#define NN 100000
#define NE 1600000
#define FD 128
#define NH 512
#define NC 64
#define SCAN_BLOCKS 98   // ceil(100000/1024)

// ---------------- device scratch (static; no allocations allowed) ----------------
__device__ int   g_deg[NN + 1];
__device__ int   g_incl[NN];
__device__ int   g_blktot[128];
__device__ int   g_blkoff[128];
__device__ int   g_rowptr[NN + 1];
__device__ int   g_cursor[NN];
__device__ int   g_col[NE];
__device__ float g_wgt[NE];
__device__ float g_ft0[NN * FD];
__device__ float g_ft1[NN * FD];
__device__ float g_h[NN * NH];
__device__ float g_colsum[NH];
__device__ float g_colsq[NH];
__device__ float g_scale[NH];
__device__ float g_shift[NH];

// ---------------- CSR build ----------------
__global__ void k_zero() {
    int i = blockIdx.x * blockDim.x + threadIdx.x;
    int st = gridDim.x * blockDim.x;
    for (int j = i; j < NN + 1; j += st) g_deg[j] = 0;
    if (i < NH) { g_colsum[i] = 0.f; g_colsq[i] = 0.f; }
}

__global__ void k_hist(const int* __restrict__ dst) {
    int e = blockIdx.x * blockDim.x + threadIdx.x;
    if (e < NE) atomicAdd(&g_deg[dst[e]], 1);
}

__global__ void k_scan1() {
    __shared__ int sh[1024];
    int i = blockIdx.x * 1024 + threadIdx.x;
    int v = (i < NN) ? g_deg[i] : 0;
    sh[threadIdx.x] = v;
    __syncthreads();
    #pragma unroll
    for (int off = 1; off < 1024; off <<= 1) {
        int t = (threadIdx.x >= off) ? sh[threadIdx.x - off] : 0;
        __syncthreads();
        sh[threadIdx.x] += t;
        __syncthreads();
    }
    if (i < NN) g_incl[i] = sh[threadIdx.x];
    if (threadIdx.x == 1023) g_blktot[blockIdx.x] = sh[1023];
}

__global__ void k_scan2() {
    if (blockIdx.x == 0 && threadIdx.x == 0) {
        int acc = 0;
        for (int b = 0; b < SCAN_BLOCKS; b++) { g_blkoff[b] = acc; acc += g_blktot[b]; }
    }
}

__global__ void k_scan3() {
    int i = blockIdx.x * blockDim.x + threadIdx.x;
    if (i < NN) {
        int excl = g_incl[i] - g_deg[i] + g_blkoff[i >> 10];
        g_rowptr[i] = excl;
        g_cursor[i] = excl;
        if (i == NN - 1) g_rowptr[NN] = g_incl[i] + g_blkoff[i >> 10];
    }
}

__global__ void k_scatter(const int* __restrict__ src, const int* __restrict__ dst,
                          const float* __restrict__ nrm) {
    int e = blockIdx.x * blockDim.x + threadIdx.x;
    if (e < NE) {
        int d = dst[e];
        int pos = atomicAdd(&g_cursor[d], 1);
        g_col[pos] = src[e];
        g_wgt[pos] = nrm[e];
    }
}

// ---------------- K-hop propagation: one warp per dst node, CSR gather-reduce ----------------
__global__ void k_prop(const float* __restrict__ feat, int mode) {
    int gt = blockIdx.x * blockDim.x + threadIdx.x;
    int node = gt >> 5;
    int lane = gt & 31;
    if (node >= NN) return;
    const float* in  = (mode == 0) ? feat : ((mode == 1) ? g_ft1 : g_ft0);
    float*       out = (mode == 1) ? g_ft0 : g_ft1;
    int beg = g_rowptr[node];
    int end = g_rowptr[node + 1];
    const float4* in4 = (const float4*)in;
    float4 acc = make_float4(0.f, 0.f, 0.f, 0.f);
    for (int j = beg; j < end; j++) {
        int   s = g_col[j];
        float w = g_wgt[j];
        float4 v = in4[s * 32 + lane];
        acc.x = fmaf(v.x, w, acc.x);
        acc.y = fmaf(v.y, w, acc.y);
        acc.z = fmaf(v.z, w, acc.z);
        acc.w = fmaf(v.w, w, acc.w);
    }
    ((float4*)out)[node * 32 + lane] = acc;
}

// ---------------- GEMM1: h = ft @ fc1_w^T + b1, [100000,128] x [512,128]^T ----------------
__global__ __launch_bounds__(256) void k_gemm1(const float* __restrict__ W,
                                               const float* __restrict__ bias) {
    __shared__ float As[16][128];
    __shared__ float Bs[16][128];
    const int m0 = blockIdx.x * 128;
    const int n0 = blockIdx.y * 128;
    const int tid = threadIdx.x;
    const int tx = tid & 15;
    const int ty = tid >> 4;
    float acc[8][8];
    #pragma unroll
    for (int i = 0; i < 8; i++)
        #pragma unroll
        for (int j = 0; j < 8; j++) acc[i][j] = 0.f;

    for (int kt = 0; kt < FD; kt += 16) {
        #pragma unroll
        for (int i = 0; i < 2; i++) {
            int idx = tid * 2 + i;
            int r = idx >> 2, c4 = idx & 3;
            int gr = m0 + r; if (gr >= NN) gr = NN - 1;
            float4 v = *(const float4*)(&g_ft1[gr * FD + kt + c4 * 4]);
            As[c4 * 4 + 0][r] = v.x; As[c4 * 4 + 1][r] = v.y;
            As[c4 * 4 + 2][r] = v.z; As[c4 * 4 + 3][r] = v.w;
            float4 w = *(const float4*)(&W[(n0 + r) * FD + kt + c4 * 4]);
            Bs[c4 * 4 + 0][r] = w.x; Bs[c4 * 4 + 1][r] = w.y;
            Bs[c4 * 4 + 2][r] = w.z; Bs[c4 * 4 + 3][r] = w.w;
        }
        __syncthreads();
        #pragma unroll
        for (int kk = 0; kk < 16; kk++) {
            float a[8], b[8];
            *(float4*)&a[0] = *(float4*)&As[kk][ty * 8];
            *(float4*)&a[4] = *(float4*)&As[kk][ty * 8 + 4];
            *(float4*)&b[0] = *(float4*)&Bs[kk][tx * 8];
            *(float4*)&b[4] = *(float4*)&Bs[kk][tx * 8 + 4];
            #pragma unroll
            for (int i = 0; i < 8; i++)
                #pragma unroll
                for (int j = 0; j < 8; j++)
                    acc[i][j] = fmaf(a[i], b[j], acc[i][j]);
        }
        __syncthreads();
    }
    #pragma unroll
    for (int i = 0; i < 8; i++) {
        int m = m0 + ty * 8 + i;
        if (m < NN) {
            #pragma unroll
            for (int j = 0; j < 8; j += 4) {
                int n = n0 + tx * 8 + j;
                float4 o;
                o.x = acc[i][j + 0] + bias[n + 0];
                o.y = acc[i][j + 1] + bias[n + 1];
                o.z = acc[i][j + 2] + bias[n + 2];
                o.w = acc[i][j + 3] + bias[n + 3];
                *(float4*)&g_h[m * NH + n] = o;
            }
        }
    }
}

// ---------------- BN stats: per-feature sum / sumsq over all rows ----------------
__global__ void k_bnstats() {
    const int col = threadIdx.x;                       // 512 threads = one per feature
    const int per = (NN + gridDim.x - 1) / gridDim.x;
    int r0 = blockIdx.x * per;
    int r1 = r0 + per; if (r1 > NN) r1 = NN;
    float s = 0.f, q = 0.f;
    for (int r = r0; r < r1; r++) {
        float v = g_h[r * NH + col];
        s += v;
        q = fmaf(v, v, q);
    }
    atomicAdd(&g_colsum[col], s);
    atomicAdd(&g_colsq[col], q);
}

__global__ void k_bnfinal(const float* __restrict__ gamma, const float* __restrict__ beta) {
    int c = blockIdx.x * blockDim.x + threadIdx.x;
    if (c < NH) {
        float mean = g_colsum[c] * (1.0f / NN);
        float var  = g_colsq[c] * (1.0f / NN) - mean * mean;
        float sc = gamma[c] * rsqrtf(var + 1e-5f);
        g_scale[c] = sc;
        g_shift[c] = beta[c] - mean * sc;
    }
}

// ---------------- GEMM2: out = relu(h*scale+shift) @ fc2_w^T + b2 ----------------
__global__ __launch_bounds__(256) void k_gemm2(const float* __restrict__ W2,
                                               const float* __restrict__ b2,
                                               float* __restrict__ out) {
    __shared__ float As[16][128];
    __shared__ float Bs[16][64];
    __shared__ float s_scale[NH];
    __shared__ float s_shift[NH];
    const int m0 = blockIdx.x * 128;
    const int tid = threadIdx.x;
    const int tx = tid & 15;   // n: 4 cols each
    const int ty = tid >> 4;   // m: 8 rows each
    for (int i = tid; i < NH; i += 256) { s_scale[i] = g_scale[i]; s_shift[i] = g_shift[i]; }
    __syncthreads();

    float acc[8][4];
    #pragma unroll
    for (int i = 0; i < 8; i++)
        #pragma unroll
        for (int j = 0; j < 4; j++) acc[i][j] = 0.f;

    for (int kt = 0; kt < NH; kt += 16) {
        #pragma unroll
        for (int i = 0; i < 2; i++) {
            int idx = tid * 2 + i;
            int r = idx >> 2, c4 = idx & 3;
            int gr = m0 + r; if (gr >= NN) gr = NN - 1;
            float4 v = *(const float4*)&g_h[gr * NH + kt + c4 * 4];
            int k = kt + c4 * 4;
            As[c4 * 4 + 0][r] = fmaxf(fmaf(v.x, s_scale[k + 0], s_shift[k + 0]), 0.f);
            As[c4 * 4 + 1][r] = fmaxf(fmaf(v.y, s_scale[k + 1], s_shift[k + 1]), 0.f);
            As[c4 * 4 + 2][r] = fmaxf(fmaf(v.z, s_scale[k + 2], s_shift[k + 2]), 0.f);
            As[c4 * 4 + 3][r] = fmaxf(fmaf(v.w, s_scale[k + 3], s_shift[k + 3]), 0.f);
        }
        {
            int r = tid >> 2, c4 = tid & 3;  // 64 rows x 4 float4
            float4 w = *(const float4*)&W2[r * NH + kt + c4 * 4];
            Bs[c4 * 4 + 0][r] = w.x; Bs[c4 * 4 + 1][r] = w.y;
            Bs[c4 * 4 + 2][r] = w.z; Bs[c4 * 4 + 3][r] = w.w;
        }
        __syncthreads();
        #pragma unroll
        for (int kk = 0; kk < 16; kk++) {
            float a[8], b[4];
            *(float4*)&a[0] = *(float4*)&As[kk][ty * 8];
            *(float4*)&a[4] = *(float4*)&As[kk][ty * 8 + 4];
            *(float4*)&b[0] = *(float4*)&Bs[kk][tx * 4];
            #pragma unroll
            for (int i = 0; i < 8; i++)
                #pragma unroll
                for (int j = 0; j < 4; j++)
                    acc[i][j] = fmaf(a[i], b[j], acc[i][j]);
        }
        __syncthreads();
    }
    #pragma unroll
    for (int i = 0; i < 8; i++) {
        int m = m0 + ty * 8 + i;
        if (m < NN) {
            int n = tx * 4;
            float4 o;
            o.x = acc[i][0] + b2[n + 0];
            o.y = acc[i][1] + b2[n + 1];
            o.z = acc[i][2] + b2[n + 2];
            o.w = acc[i][3] + b2[n + 3];
            *(float4*)&out[m * NC + n] = o;
        }
    }
}

// ---------------- host launch ----------------
extern "C" void kernel_launch(void* const* d_in, const int* in_sizes, int n_in,
                              void* d_out, int out_size) {
    const float* feat   = (const float*)d_in[0];
    const int*   src    = (const int*)d_in[1];
    const int*   dst    = (const int*)d_in[2];
    const float* nrm    = (const float*)d_in[3];
    const float* fc1_w  = (const float*)d_in[4];
    const float* fc1_b  = (const float*)d_in[5];
    const float* gamma  = (const float*)d_in[6];
    const float* beta   = (const float*)d_in[7];
    const float* fc2_w  = (const float*)d_in[8];
    const float* fc2_b  = (const float*)d_in[9];
    float* out = (float*)d_out;

    // CSR build (per launch, deterministic up to fp add order)
    k_zero<<<256, 256>>>();
    k_hist<<<(NE + 255) / 256, 256>>>(dst);
    k_scan1<<<SCAN_BLOCKS, 1024>>>();
    k_scan2<<<1, 32>>>();
    k_scan3<<<(NN + 255) / 256, 256>>>();
    k_scatter<<<(NE + 255) / 256, 256>>>(src, dst, nrm);

    // 3-hop propagation: feat -> ft1 -> ft0 -> ft1
    int prop_blocks = (NN * 32 + 255) / 256;
    k_prop<<<prop_blocks, 256>>>(feat, 0);
    k_prop<<<prop_blocks, 256>>>(feat, 1);
    k_prop<<<prop_blocks, 256>>>(feat, 2);

    // MLP
    dim3 g1((NN + 127) / 128, NH / 128);
    k_gemm1<<<g1, 256>>>(fc1_w, fc1_b);
    k_bnstats<<<200, NH>>>();
    k_bnfinal<<<2, 256>>>(gamma, beta);
    k_gemm2<<<(NN + 127) / 128, 256>>>(fc2_w, fc2_b, out);
}

// round 2
// speedup vs baseline: 1.5343x; 1.5343x over previous
#include <cuda_runtime.h>

#define NN 100000
#define NE 1600000
#define FD 128
#define NH 512
#define NC 64
#define SCAN_BLOCKS 98   // ceil(100000/1024)

// ---------------- device scratch (static; no allocations allowed) ----------------
__device__ int   g_deg[NN + 1];
__device__ int   g_incl[NN];
__device__ int   g_blktot[128];
__device__ int   g_blkoff[128];
__device__ int   g_rowptr[NN + 1];
__device__ int   g_cursor[NN];
__device__ int   g_col[NE];
__device__ float g_wgt[NE];
__device__ float g_ft0[NN * FD];
__device__ float g_ft1[NN * FD];
__device__ float g_h[NN * NH];
__device__ float g_colsum[NH];
__device__ float g_colsq[NH];
__device__ float g_scale[NH];
__device__ float g_shift[NH];

// ---------------- tf32 mma helpers ----------------
__device__ __forceinline__ unsigned f2tf32(float x) {
    unsigned u;
    asm("cvt.rna.tf32.f32 %0, %1;" : "=r"(u) : "f"(x));
    return u;
}

__device__ __forceinline__ void mma_tf32(float* c, const unsigned* a, const unsigned* b) {
    asm volatile(
        "mma.sync.aligned.m16n8k8.row.col.f32.tf32.tf32.f32 "
        "{%0,%1,%2,%3}, {%4,%5,%6,%7}, {%8,%9}, {%0,%1,%2,%3};"
        : "+f"(c[0]), "+f"(c[1]), "+f"(c[2]), "+f"(c[3])
        : "r"(a[0]), "r"(a[1]), "r"(a[2]), "r"(a[3]), "r"(b[0]), "r"(b[1]));
}

// ---------------- CSR build ----------------
__global__ void k_zero() {
    int i = blockIdx.x * blockDim.x + threadIdx.x;
    int st = gridDim.x * blockDim.x;
    for (int j = i; j < NN + 1; j += st) g_deg[j] = 0;
    if (i < NH) { g_colsum[i] = 0.f; g_colsq[i] = 0.f; }
}

__global__ void k_hist(const int* __restrict__ dst) {
    int e = blockIdx.x * blockDim.x + threadIdx.x;
    if (e < NE) atomicAdd(&g_deg[dst[e]], 1);
}

__global__ void k_scan1() {
    __shared__ int sh[1024];
    int i = blockIdx.x * 1024 + threadIdx.x;
    int v = (i < NN) ? g_deg[i] : 0;
    sh[threadIdx.x] = v;
    __syncthreads();
    #pragma unroll
    for (int off = 1; off < 1024; off <<= 1) {
        int t = (threadIdx.x >= off) ? sh[threadIdx.x - off] : 0;
        __syncthreads();
        sh[threadIdx.x] += t;
        __syncthreads();
    }
    if (i < NN) g_incl[i] = sh[threadIdx.x];
    if (threadIdx.x == 1023) g_blktot[blockIdx.x] = sh[1023];
}

__global__ void k_scan2() {   // 1 block, 128 threads: parallel scan of block totals
    __shared__ int sh[128];
    int v = (threadIdx.x < SCAN_BLOCKS) ? g_blktot[threadIdx.x] : 0;
    sh[threadIdx.x] = v;
    __syncthreads();
    #pragma unroll
    for (int off = 1; off < 128; off <<= 1) {
        int t = (threadIdx.x >= off) ? sh[threadIdx.x - off] : 0;
        __syncthreads();
        sh[threadIdx.x] += t;
        __syncthreads();
    }
    if (threadIdx.x < SCAN_BLOCKS) g_blkoff[threadIdx.x] = sh[threadIdx.x] - v;
}

__global__ void k_scan3() {
    int i = blockIdx.x * blockDim.x + threadIdx.x;
    if (i < NN) {
        int excl = g_incl[i] - g_deg[i] + g_blkoff[i >> 10];
        g_rowptr[i] = excl;
        g_cursor[i] = excl;
        if (i == NN - 1) g_rowptr[NN] = g_incl[i] + g_blkoff[i >> 10];
    }
}

__global__ void k_scatter(const int* __restrict__ src, const int* __restrict__ dst,
                          const float* __restrict__ nrm) {
    int e = blockIdx.x * blockDim.x + threadIdx.x;
    if (e < NE) {
        int d = dst[e];
        int pos = atomicAdd(&g_cursor[d], 1);
        g_col[pos] = src[e];
        g_wgt[pos] = nrm[e];
    }
}

// ---------------- K-hop propagation: one warp per dst node, CSR gather-reduce ----------------
__global__ void k_prop(const float* __restrict__ feat, int mode) {
    int gt = blockIdx.x * blockDim.x + threadIdx.x;
    int node = gt >> 5;
    int lane = gt & 31;
    if (node >= NN) return;
    const float* in  = (mode == 0) ? feat : ((mode == 1) ? g_ft1 : g_ft0);
    float*       out = (mode == 1) ? g_ft0 : g_ft1;
    int beg = g_rowptr[node];
    int end = g_rowptr[node + 1];
    const float4* in4 = (const float4*)in;
    float4 acc = make_float4(0.f, 0.f, 0.f, 0.f);
    for (int j = beg; j < end; j++) {
        int   s = g_col[j];
        float w = g_wgt[j];
        float4 v = in4[s * 32 + lane];
        acc.x = fmaf(v.x, w, acc.x);
        acc.y = fmaf(v.y, w, acc.y);
        acc.z = fmaf(v.z, w, acc.z);
        acc.w = fmaf(v.w, w, acc.w);
    }
    ((float4*)out)[node * 32 + lane] = acc;
}

// ---------------- GEMM1 (tf32 MMA): h = ft1 @ fc1_w^T + b1, fused BN stats ----------------
// Block tile 128x128, 8 warps as 2(M)x4(N), warp tile 64x32; BK=16.
#define AS1 20     // As stride: 20g%32 = {0,20,8,28,16,4,24,12} + t -> conflict-free
#define BS1 136    // Bs stride: 136%32 = 8 -> 8t+g -> conflict-free
__global__ __launch_bounds__(256) void k_gemm1(const float* __restrict__ W,
                                               const float* __restrict__ bias) {
    __shared__ unsigned As[128 * AS1];
    __shared__ unsigned Bs[16 * BS1];
    __shared__ float s_bias[128];
    const int tid = threadIdx.x;
    const int m0 = blockIdx.x * 128, n0 = blockIdx.y * 128;
    const int wid = tid >> 5, lane = tid & 31;
    const int g = lane >> 2, t = lane & 3;
    const int wm = (wid & 1) * 64, wn = (wid >> 1) * 32;
    if (tid < 128) s_bias[tid] = bias[n0 + tid];

    float acc[4][4][4];
    #pragma unroll
    for (int i = 0; i < 4; i++)
        #pragma unroll
        for (int j = 0; j < 4; j++)
            #pragma unroll
            for (int r = 0; r < 4; r++) acc[i][j][r] = 0.f;

    const int lrow = tid >> 1, lkq = (tid & 1) * 8;
    for (int kt = 0; kt < FD; kt += 16) {
        // A tile: 128 rows x 16 k
        {
            int gr = m0 + lrow; if (gr >= NN) gr = NN - 1;
            float4 v0 = *(const float4*)&g_ft1[gr * FD + kt + lkq];
            float4 v1 = *(const float4*)&g_ft1[gr * FD + kt + lkq + 4];
            unsigned* a = &As[lrow * AS1 + lkq];
            a[0] = f2tf32(v0.x); a[1] = f2tf32(v0.y); a[2] = f2tf32(v0.z); a[3] = f2tf32(v0.w);
            a[4] = f2tf32(v1.x); a[5] = f2tf32(v1.y); a[6] = f2tf32(v1.z); a[7] = f2tf32(v1.w);
        }
        // B tile: Bs[k][n] = W[n0+n][kt+k], 128 n x 16 k
        {
            int n = lrow;
            float4 w0 = *(const float4*)&W[(n0 + n) * FD + kt + lkq];
            float4 w1 = *(const float4*)&W[(n0 + n) * FD + kt + lkq + 4];
            Bs[(lkq + 0) * BS1 + n] = f2tf32(w0.x);
            Bs[(lkq + 1) * BS1 + n] = f2tf32(w0.y);
            Bs[(lkq + 2) * BS1 + n] = f2tf32(w0.z);
            Bs[(lkq + 3) * BS1 + n] = f2tf32(w0.w);
            Bs[(lkq + 4) * BS1 + n] = f2tf32(w1.x);
            Bs[(lkq + 5) * BS1 + n] = f2tf32(w1.y);
            Bs[(lkq + 6) * BS1 + n] = f2tf32(w1.z);
            Bs[(lkq + 7) * BS1 + n] = f2tf32(w1.w);
        }
        __syncthreads();
        #pragma unroll
        for (int ks = 0; ks < 16; ks += 8) {
            unsigned bf[4][2];
            #pragma unroll
            for (int j = 0; j < 4; j++) {
                bf[j][0] = Bs[(ks + t) * BS1 + wn + 8 * j + g];
                bf[j][1] = Bs[(ks + t + 4) * BS1 + wn + 8 * j + g];
            }
            #pragma unroll
            for (int i = 0; i < 4; i++) {
                unsigned af[4];
                af[0] = As[(wm + 16 * i + g) * AS1 + ks + t];
                af[1] = As[(wm + 16 * i + 8 + g) * AS1 + ks + t];
                af[2] = As[(wm + 16 * i + g) * AS1 + ks + t + 4];
                af[3] = As[(wm + 16 * i + 8 + g) * AS1 + ks + t + 4];
                #pragma unroll
                for (int j = 0; j < 4; j++) mma_tf32(acc[i][j], af, bf[j]);
            }
        }
        __syncthreads();
    }

    // Epilogue: bias add, write h, fused BN partial sums (masked to valid rows)
    float s0[4] = {0.f,0.f,0.f,0.f}, q0[4] = {0.f,0.f,0.f,0.f};
    float s1[4] = {0.f,0.f,0.f,0.f}, q1[4] = {0.f,0.f,0.f,0.f};
    #pragma unroll
    for (int i = 0; i < 4; i++) {
        int r0 = m0 + wm + 16 * i + g;
        int r1 = r0 + 8;
        #pragma unroll
        for (int j = 0; j < 4; j++) {
            int lc = wn + 8 * j + 2 * t;
            float b0v = s_bias[lc], b1v = s_bias[lc + 1];
            float h00 = acc[i][j][0] + b0v, h01 = acc[i][j][1] + b1v;
            float h10 = acc[i][j][2] + b0v, h11 = acc[i][j][3] + b1v;
            if (r0 < NN) {
                *(float2*)&g_h[r0 * NH + n0 + lc] = make_float2(h00, h01);
                s0[j] += h00; q0[j] = fmaf(h00, h00, q0[j]);
                s1[j] += h01; q1[j] = fmaf(h01, h01, q1[j]);
            }
            if (r1 < NN) {
                *(float2*)&g_h[r1 * NH + n0 + lc] = make_float2(h10, h11);
                s0[j] += h10; q0[j] = fmaf(h10, h10, q0[j]);
                s1[j] += h11; q1[j] = fmaf(h11, h11, q1[j]);
            }
        }
    }
    // reduce over g-dimension (lanes xor 4,8,16 keep t fixed)
    #pragma unroll
    for (int j = 0; j < 4; j++) {
        #pragma unroll
        for (int off = 4; off < 32; off <<= 1) {
            s0[j] += __shfl_xor_sync(0xffffffff, s0[j], off);
            q0[j] += __shfl_xor_sync(0xffffffff, q0[j], off);
            s1[j] += __shfl_xor_sync(0xffffffff, s1[j], off);
            q1[j] += __shfl_xor_sync(0xffffffff, q1[j], off);
        }
    }
    if (lane < 4) {
        #pragma unroll
        for (int j = 0; j < 4; j++) {
            int col = n0 + wn + 8 * j + 2 * lane;
            atomicAdd(&g_colsum[col],     s0[j]);
            atomicAdd(&g_colsum[col + 1], s1[j]);
            atomicAdd(&g_colsq[col],      q0[j]);
            atomicAdd(&g_colsq[col + 1],  q1[j]);
        }
    }
}

__global__ void k_bnfinal(const float* __restrict__ gamma, const float* __restrict__ beta) {
    int c = blockIdx.x * blockDim.x + threadIdx.x;
    if (c < NH) {
        float mean = g_colsum[c] * (1.0f / NN);
        float var  = g_colsq[c] * (1.0f / NN) - mean * mean;
        float sc = gamma[c] * rsqrtf(var + 1e-5f);
        g_scale[c] = sc;
        g_shift[c] = beta[c] - mean * sc;
    }
}

// ---------------- GEMM2 (tf32 MMA): out = relu(h*scale+shift) @ fc2_w^T + b2 ----------------
// Block tile 128x64, 8 warps as 4(M)x2(N), warp tile 32x32; BK=16, K=512.
#define BS2 72     // 72%32 = 8 -> conflict-free
__global__ __launch_bounds__(256) void k_gemm2(const float* __restrict__ W2,
                                               const float* __restrict__ b2,
                                               float* __restrict__ out) {
    __shared__ unsigned As[128 * AS1];
    __shared__ unsigned Bs[16 * BS2];
    __shared__ float s_scale[NH];
    __shared__ float s_shift[NH];
    __shared__ float s_b2[NC];
    const int tid = threadIdx.x;
    const int m0 = blockIdx.x * 128;
    const int wid = tid >> 5, lane = tid & 31;
    const int g = lane >> 2, t = lane & 3;
    const int wm = (wid & 3) * 32, wn = (wid >> 2) * 32;
    for (int i = tid; i < NH; i += 256) { s_scale[i] = g_scale[i]; s_shift[i] = g_shift[i]; }
    if (tid < NC) s_b2[tid] = b2[tid];
    __syncthreads();

    float acc[2][4][4];
    #pragma unroll
    for (int i = 0; i < 2; i++)
        #pragma unroll
        for (int j = 0; j < 4; j++)
            #pragma unroll
            for (int r = 0; r < 4; r++) acc[i][j][r] = 0.f;

    const int lrow = tid >> 1, lkq = (tid & 1) * 8;
    for (int kt = 0; kt < NH; kt += 16) {
        // A tile: fused BN + ReLU
        {
            int gr = m0 + lrow; if (gr >= NN) gr = NN - 1;
            float4 v0 = *(const float4*)&g_h[gr * NH + kt + lkq];
            float4 v1 = *(const float4*)&g_h[gr * NH + kt + lkq + 4];
            int k = kt + lkq;
            unsigned* a = &As[lrow * AS1 + lkq];
            a[0] = f2tf32(fmaxf(fmaf(v0.x, s_scale[k+0], s_shift[k+0]), 0.f));
            a[1] = f2tf32(fmaxf(fmaf(v0.y, s_scale[k+1], s_shift[k+1]), 0.f));
            a[2] = f2tf32(fmaxf(fmaf(v0.z, s_scale[k+2], s_shift[k+2]), 0.f));
            a[3] = f2tf32(fmaxf(fmaf(v0.w, s_scale[k+3], s_shift[k+3]), 0.f));
            a[4] = f2tf32(fmaxf(fmaf(v1.x, s_scale[k+4], s_shift[k+4]), 0.f));
            a[5] = f2tf32(fmaxf(fmaf(v1.y, s_scale[k+5], s_shift[k+5]), 0.f));
            a[6] = f2tf32(fmaxf(fmaf(v1.z, s_scale[k+6], s_shift[k+6]), 0.f));
            a[7] = f2tf32(fmaxf(fmaf(v1.w, s_scale[k+7], s_shift[k+7]), 0.f));
        }
        // B tile: Bs[k][n] = W2[n][kt+k], 64 n x 16 k
        if (tid < 128) {
            int n = tid >> 1;
            float4 w0 = *(const float4*)&W2[n * NH + kt + lkq];
            float4 w1 = *(const float4*)&W2[n * NH + kt + lkq + 4];
            Bs[(lkq + 0) * BS2 + n] = f2tf32(w0.x);
            Bs[(lkq + 1) * BS2 + n] = f2tf32(w0.y);
            Bs[(lkq + 2) * BS2 + n] = f2tf32(w0.z);
            Bs[(lkq + 3) * BS2 + n] = f2tf32(w0.w);
            Bs[(lkq + 4) * BS2 + n] = f2tf32(w1.x);
            Bs[(lkq + 5) * BS2 + n] = f2tf32(w1.y);
            Bs[(lkq + 6) * BS2 + n] = f2tf32(w1.z);
            Bs[(lkq + 7) * BS2 + n] = f2tf32(w1.w);
        }
        __syncthreads();
        #pragma unroll
        for (int ks = 0; ks < 16; ks += 8) {
            unsigned bf[4][2];
            #pragma unroll
            for (int j = 0; j < 4; j++) {
                bf[j][0] = Bs[(ks + t) * BS2 + wn + 8 * j + g];
                bf[j][1] = Bs[(ks + t + 4) * BS2 + wn + 8 * j + g];
            }
            #pragma unroll
            for (int i = 0; i < 2; i++) {
                unsigned af[4];
                af[0] = As[(wm + 16 * i + g) * AS1 + ks + t];
                af[1] = As[(wm + 16 * i + 8 + g) * AS1 + ks + t];
                af[2] = As[(wm + 16 * i + g) * AS1 + ks + t + 4];
                af[3] = As[(wm + 16 * i + 8 + g) * AS1 + ks + t + 4];
                #pragma unroll
                for (int j = 0; j < 4; j++) mma_tf32(acc[i][j], af, bf[j]);
            }
        }
        __syncthreads();
    }
    #pragma unroll
    for (int i = 0; i < 2; i++) {
        int r0 = m0 + wm + 16 * i + g;
        int r1 = r0 + 8;
        #pragma unroll
        for (int j = 0; j < 4; j++) {
            int col = wn + 8 * j + 2 * t;
            float b0v = s_b2[col], b1v = s_b2[col + 1];
            if (r0 < NN)
                *(float2*)&out[r0 * NC + col] = make_float2(acc[i][j][0] + b0v, acc[i][j][1] + b1v);
            if (r1 < NN)
                *(float2*)&out[r1 * NC + col] = make_float2(acc[i][j][2] + b0v, acc[i][j][3] + b1v);
        }
    }
}

// ---------------- host launch ----------------
extern "C" void kernel_launch(void* const* d_in, const int* in_sizes, int n_in,
                              void* d_out, int out_size) {
    const float* feat   = (const float*)d_in[0];
    const int*   src    = (const int*)d_in[1];
    const int*   dst    = (const int*)d_in[2];
    const float* nrm    = (const float*)d_in[3];
    const float* fc1_w  = (const float*)d_in[4];
    const float* fc1_b  = (const float*)d_in[5];
    const float* gamma  = (const float*)d_in[6];
    const float* beta   = (const float*)d_in[7];
    const float* fc2_w  = (const float*)d_in[8];
    const float* fc2_b  = (const float*)d_in[9];
    float* out = (float*)d_out;

    // CSR build
    k_zero<<<256, 256>>>();
    k_hist<<<(NE + 255) / 256, 256>>>(dst);
    k_scan1<<<SCAN_BLOCKS, 1024>>>();
    k_scan2<<<1, 128>>>();
    k_scan3<<<(NN + 255) / 256, 256>>>();
    k_scatter<<<(NE + 255) / 256, 256>>>(src, dst, nrm);

    // 3-hop propagation: feat -> ft1 -> ft0 -> ft1
    int prop_blocks = (NN * 32 + 255) / 256;
    k_prop<<<prop_blocks, 256>>>(feat, 0);
    k_prop<<<prop_blocks, 256>>>(feat, 1);
    k_prop<<<prop_blocks, 256>>>(feat, 2);

    // MLP (tf32 tensor-core GEMMs, BN stats fused into GEMM1)
    dim3 g1((NN + 127) / 128, NH / 128);
    k_gemm1<<<g1, 256>>>(fc1_w, fc1_b);
    k_bnfinal<<<2, 256>>>(gamma, beta);
    k_gemm2<<<(NN + 127) / 128, 256>>>(fc2_w, fc2_b, out);
}

// round 3
// speedup vs baseline: 2.2233x; 1.4490x over previous
#include <cuda_runtime.h>
#include <cuda_fp16.h>

#define NN 100000
#define NE 1600000
#define FD 128
#define NH 512
#define NC 64
#define SCAN_BLOCKS 98   // ceil(100000/1024)

// ---------------- device scratch ----------------
__device__ int    g_deg[NN + 1];
__device__ int    g_incl[NN];
__device__ int    g_blktot[128];
__device__ int    g_blkoff[128];
__device__ int    g_rowptr[NN + 1];
__device__ int    g_cursor[NN];
__device__ int    g_col[NE];
__device__ float  g_wgt[NE];
__device__ __half g_fh0[NN * FD];   // fp16 feature ping
__device__ __half g_fh1[NN * FD];   // fp16 feature pong
__device__ __half g_hh[NN * NH];    // fp16 hidden
__device__ float  g_colsum[NH];
__device__ float  g_colsq[NH];
__device__ float  g_scale[NH];
__device__ float  g_shift[NH];

// ---------------- fp16 mma helper (m16n8k16, fp32 accum) ----------------
__device__ __forceinline__ void mma_f16(float* c, const unsigned* a, const unsigned* b) {
    asm volatile(
        "mma.sync.aligned.m16n8k16.row.col.f32.f16.f16.f32 "
        "{%0,%1,%2,%3}, {%4,%5,%6,%7}, {%8,%9}, {%0,%1,%2,%3};"
        : "+f"(c[0]), "+f"(c[1]), "+f"(c[2]), "+f"(c[3])
        : "r"(a[0]), "r"(a[1]), "r"(a[2]), "r"(a[3]), "r"(b[0]), "r"(b[1]));
}

// ---------------- CSR build ----------------
__global__ void k_zero() {
    int i = blockIdx.x * blockDim.x + threadIdx.x;
    int st = gridDim.x * blockDim.x;
    for (int j = i; j < NN + 1; j += st) g_deg[j] = 0;
    if (i < NH) { g_colsum[i] = 0.f; g_colsq[i] = 0.f; }
}

__global__ void k_hist(const int* __restrict__ dst) {
    int e = blockIdx.x * blockDim.x + threadIdx.x;
    if (e < NE) atomicAdd(&g_deg[dst[e]], 1);
}

__global__ void k_scan1() {
    __shared__ int sh[1024];
    int i = blockIdx.x * 1024 + threadIdx.x;
    int v = (i < NN) ? g_deg[i] : 0;
    sh[threadIdx.x] = v;
    __syncthreads();
    #pragma unroll
    for (int off = 1; off < 1024; off <<= 1) {
        int t = (threadIdx.x >= off) ? sh[threadIdx.x - off] : 0;
        __syncthreads();
        sh[threadIdx.x] += t;
        __syncthreads();
    }
    if (i < NN) g_incl[i] = sh[threadIdx.x];
    if (threadIdx.x == 1023) g_blktot[blockIdx.x] = sh[1023];
}

__global__ void k_scan2() {
    __shared__ int sh[128];
    int v = (threadIdx.x < SCAN_BLOCKS) ? g_blktot[threadIdx.x] : 0;
    sh[threadIdx.x] = v;
    __syncthreads();
    #pragma unroll
    for (int off = 1; off < 128; off <<= 1) {
        int t = (threadIdx.x >= off) ? sh[threadIdx.x - off] : 0;
        __syncthreads();
        sh[threadIdx.x] += t;
        __syncthreads();
    }
    if (threadIdx.x < SCAN_BLOCKS) g_blkoff[threadIdx.x] = sh[threadIdx.x] - v;
}

__global__ void k_scan3() {
    int i = blockIdx.x * blockDim.x + threadIdx.x;
    if (i < NN) {
        int excl = g_incl[i] - g_deg[i] + g_blkoff[i >> 10];
        g_rowptr[i] = excl;
        g_cursor[i] = excl;
        if (i == NN - 1) g_rowptr[NN] = g_incl[i] + g_blkoff[i >> 10];
    }
}

__global__ void k_scatter(const int* __restrict__ src, const int* __restrict__ dst,
                          const float* __restrict__ nrm) {
    int e = blockIdx.x * blockDim.x + threadIdx.x;
    if (e < NE) {
        int d = dst[e];
        int pos = atomicAdd(&g_cursor[d], 1);
        g_col[pos] = src[e];
        g_wgt[pos] = nrm[e];
    }
}

// ---------------- feat fp32 -> fp16 ----------------
__global__ void k_cvt(const float* __restrict__ feat) {
    int i = blockIdx.x * blockDim.x + threadIdx.x;   // one half2 per thread
    if (i < NN * FD / 2) {
        float2 v = ((const float2*)feat)[i];
        ((__half2*)g_fh1)[i] = __float22half2_rn(v);
    }
}

// ---------------- K-hop propagation: warp per dst, fp16 rows, fp32 accumulate ----------------
__global__ void k_prop(int par) {
    int gt = blockIdx.x * blockDim.x + threadIdx.x;
    int node = gt >> 5;
    int lane = gt & 31;
    if (node >= NN) return;
    const uint2* in2  = (const uint2*)(par ? g_fh0 : g_fh1);
    uint2*       out2 = (uint2*)(par ? g_fh1 : g_fh0);
    int beg = g_rowptr[node];
    int end = g_rowptr[node + 1];
    float4 acc = make_float4(0.f, 0.f, 0.f, 0.f);
    for (int j = beg; j < end; j++) {
        int   s = g_col[j];
        float w = g_wgt[j];
        uint2 v = in2[s * 32 + lane];
        float2 f0 = __half22float2(*(__half2*)&v.x);
        float2 f1 = __half22float2(*(__half2*)&v.y);
        acc.x = fmaf(f0.x, w, acc.x);
        acc.y = fmaf(f0.y, w, acc.y);
        acc.z = fmaf(f1.x, w, acc.z);
        acc.w = fmaf(f1.y, w, acc.w);
    }
    uint2 o;
    *(__half2*)&o.x = __float22half2_rn(make_float2(acc.x, acc.y));
    *(__half2*)&o.y = __float22half2_rn(make_float2(acc.z, acc.w));
    out2[node * 32 + lane] = o;
}

// ---------------- GEMM1 (fp16 MMA): h = ft @ W1^T + b1, fused BN stats ----------------
// Block 128x128, BK=32; 8 warps 2(M)x4(N); warp tile 64x32.
#define S1 40   // smem stride in halves: (S1/2)=20 -> 20r+t distinct mod 32 -> conflict-free
__global__ __launch_bounds__(256) void k_gemm1(const float* __restrict__ W,
                                               const float* __restrict__ bias) {
    __shared__ __half As[128 * S1];
    __shared__ __half Bs[128 * S1];
    __shared__ float s_bias[128];
    const int tid = threadIdx.x;
    const int m0 = blockIdx.x * 128, n0 = blockIdx.y * 128;
    const int wid = tid >> 5, lane = tid & 31;
    const int g = lane >> 2, t = lane & 3;
    const int wm = (wid & 1) * 64, wn = (wid >> 1) * 32;
    if (tid < 128) s_bias[tid] = bias[n0 + tid];

    float acc[4][4][4];
    #pragma unroll
    for (int i = 0; i < 4; i++)
        #pragma unroll
        for (int j = 0; j < 4; j++)
            #pragma unroll
            for (int r = 0; r < 4; r++) acc[i][j][r] = 0.f;

    const int lrow = tid >> 1, lkq = (tid & 1) * 16;
    for (int kt = 0; kt < FD; kt += 32) {
        // A: 128 rows x 32 halves (fp16 direct copy)
        {
            int gr = m0 + lrow; if (gr >= NN) gr = NN - 1;
            *(uint4*)&As[lrow * S1 + lkq]     = *(const uint4*)&g_fh0[gr * FD + kt + lkq];
            *(uint4*)&As[lrow * S1 + lkq + 8] = *(const uint4*)&g_fh0[gr * FD + kt + lkq + 8];
        }
        // B: Bs[n][k], W fp32 -> fp16
        {
            const float4* wp = (const float4*)&W[(n0 + lrow) * FD + kt + lkq];
            float4 w0 = wp[0], w1 = wp[1], w2 = wp[2], w3 = wp[3];
            __half2 p0 = __float22half2_rn(make_float2(w0.x, w0.y));
            __half2 p1 = __float22half2_rn(make_float2(w0.z, w0.w));
            __half2 p2 = __float22half2_rn(make_float2(w1.x, w1.y));
            __half2 p3 = __float22half2_rn(make_float2(w1.z, w1.w));
            __half2 p4 = __float22half2_rn(make_float2(w2.x, w2.y));
            __half2 p5 = __float22half2_rn(make_float2(w2.z, w2.w));
            __half2 p6 = __float22half2_rn(make_float2(w3.x, w3.y));
            __half2 p7 = __float22half2_rn(make_float2(w3.z, w3.w));
            uint4 u0, u1;
            u0.x = *(unsigned*)&p0; u0.y = *(unsigned*)&p1; u0.z = *(unsigned*)&p2; u0.w = *(unsigned*)&p3;
            u1.x = *(unsigned*)&p4; u1.y = *(unsigned*)&p5; u1.z = *(unsigned*)&p6; u1.w = *(unsigned*)&p7;
            *(uint4*)&Bs[lrow * S1 + lkq]     = u0;
            *(uint4*)&Bs[lrow * S1 + lkq + 8] = u1;
        }
        __syncthreads();
        #pragma unroll
        for (int ks = 0; ks < 32; ks += 16) {
            unsigned bf[4][2];
            #pragma unroll
            for (int j = 0; j < 4; j++) {
                bf[j][0] = *(unsigned*)&Bs[(wn + 8 * j + g) * S1 + ks + 2 * t];
                bf[j][1] = *(unsigned*)&Bs[(wn + 8 * j + g) * S1 + ks + 2 * t + 8];
            }
            #pragma unroll
            for (int i = 0; i < 4; i++) {
                unsigned af[4];
                af[0] = *(unsigned*)&As[(wm + 16 * i + g) * S1 + ks + 2 * t];
                af[1] = *(unsigned*)&As[(wm + 16 * i + 8 + g) * S1 + ks + 2 * t];
                af[2] = *(unsigned*)&As[(wm + 16 * i + g) * S1 + ks + 2 * t + 8];
                af[3] = *(unsigned*)&As[(wm + 16 * i + 8 + g) * S1 + ks + 2 * t + 8];
                #pragma unroll
                for (int j = 0; j < 4; j++) mma_f16(acc[i][j], af, bf[j]);
            }
        }
        __syncthreads();
    }

    // Epilogue: bias, write h (fp16), fused BN partials (fp32, masked)
    float s0[4] = {0.f,0.f,0.f,0.f}, q0[4] = {0.f,0.f,0.f,0.f};
    float s1[4] = {0.f,0.f,0.f,0.f}, q1[4] = {0.f,0.f,0.f,0.f};
    #pragma unroll
    for (int i = 0; i < 4; i++) {
        int r0 = m0 + wm + 16 * i + g;
        int r1 = r0 + 8;
        #pragma unroll
        for (int j = 0; j < 4; j++) {
            int lc = wn + 8 * j + 2 * t;
            float b0v = s_bias[lc], b1v = s_bias[lc + 1];
            float h00 = acc[i][j][0] + b0v, h01 = acc[i][j][1] + b1v;
            float h10 = acc[i][j][2] + b0v, h11 = acc[i][j][3] + b1v;
            if (r0 < NN) {
                *(__half2*)&g_hh[r0 * NH + n0 + lc] = __float22half2_rn(make_float2(h00, h01));
                s0[j] += h00; q0[j] = fmaf(h00, h00, q0[j]);
                s1[j] += h01; q1[j] = fmaf(h01, h01, q1[j]);
            }
            if (r1 < NN) {
                *(__half2*)&g_hh[r1 * NH + n0 + lc] = __float22half2_rn(make_float2(h10, h11));
                s0[j] += h10; q0[j] = fmaf(h10, h10, q0[j]);
                s1[j] += h11; q1[j] = fmaf(h11, h11, q1[j]);
            }
        }
    }
    #pragma unroll
    for (int j = 0; j < 4; j++) {
        #pragma unroll
        for (int off = 4; off < 32; off <<= 1) {
            s0[j] += __shfl_xor_sync(0xffffffff, s0[j], off);
            q0[j] += __shfl_xor_sync(0xffffffff, q0[j], off);
            s1[j] += __shfl_xor_sync(0xffffffff, s1[j], off);
            q1[j] += __shfl_xor_sync(0xffffffff, q1[j], off);
        }
    }
    if (lane < 4) {
        #pragma unroll
        for (int j = 0; j < 4; j++) {
            int col = n0 + wn + 8 * j + 2 * lane;
            atomicAdd(&g_colsum[col],     s0[j]);
            atomicAdd(&g_colsum[col + 1], s1[j]);
            atomicAdd(&g_colsq[col],      q0[j]);
            atomicAdd(&g_colsq[col + 1],  q1[j]);
        }
    }
}

__global__ void k_bnfinal(const float* __restrict__ gamma, const float* __restrict__ beta) {
    int c = blockIdx.x * blockDim.x + threadIdx.x;
    if (c < NH) {
        float mean = g_colsum[c] * (1.0f / NN);
        float var  = g_colsq[c] * (1.0f / NN) - mean * mean;
        float sc = gamma[c] * rsqrtf(var + 1e-5f);
        g_scale[c] = sc;
        g_shift[c] = beta[c] - mean * sc;
    }
}

// ---------------- GEMM2 (fp16 MMA): out = relu(h*scale+shift) @ W2^T + b2 ----------------
// Block 128x64, BK=32; 8 warps 4(M)x2(N); warp tile 32x32.
__global__ __launch_bounds__(256) void k_gemm2(const float* __restrict__ W2,
                                               const float* __restrict__ b2,
                                               float* __restrict__ out) {
    __shared__ __half As[128 * S1];
    __shared__ __half Bs[64 * S1];
    __shared__ float s_scale[NH];
    __shared__ float s_shift[NH];
    __shared__ float s_b2[NC];
    const int tid = threadIdx.x;
    const int m0 = blockIdx.x * 128;
    const int wid = tid >> 5, lane = tid & 31;
    const int g = lane >> 2, t = lane & 3;
    const int wm = (wid & 3) * 32, wn = (wid >> 2) * 32;
    for (int i = tid; i < NH; i += 256) { s_scale[i] = g_scale[i]; s_shift[i] = g_shift[i]; }
    if (tid < NC) s_b2[tid] = b2[tid];
    __syncthreads();

    float acc[2][4][4];
    #pragma unroll
    for (int i = 0; i < 2; i++)
        #pragma unroll
        for (int j = 0; j < 4; j++)
            #pragma unroll
            for (int r = 0; r < 4; r++) acc[i][j][r] = 0.f;

    const int lrow = tid >> 1, lkq = (tid & 1) * 16;
    const int brow = tid >> 2, bkq = (tid & 3) * 8;
    for (int kt = 0; kt < NH; kt += 32) {
        // A tile with fused BN+ReLU: 128 rows x 32 halves
        {
            int gr = m0 + lrow; if (gr >= NN) gr = NN - 1;
            #pragma unroll
            for (int q = 0; q < 2; q++) {
                uint4 v = *(const uint4*)&g_hh[gr * NH + kt + lkq + q * 8];
                const unsigned* vp = (const unsigned*)&v;
                unsigned res[4];
                #pragma unroll
                for (int p = 0; p < 4; p++) {
                    int k = kt + lkq + q * 8 + p * 2;
                    float2 f = __half22float2(*(__half2*)&vp[p]);
                    f.x = fmaxf(fmaf(f.x, s_scale[k],     s_shift[k]),     0.f);
                    f.y = fmaxf(fmaf(f.y, s_scale[k + 1], s_shift[k + 1]), 0.f);
                    __half2 h = __float22half2_rn(f);
                    res[p] = *(unsigned*)&h;
                }
                *(uint4*)&As[lrow * S1 + lkq + q * 8] = *(uint4*)res;
            }
        }
        // B tile: Bs[n][k], 64 n x 32 k; W2 fp32 -> fp16
        {
            const float4* wp = (const float4*)&W2[brow * NH + kt + bkq];
            float4 w0 = wp[0], w1 = wp[1];
            __half2 p0 = __float22half2_rn(make_float2(w0.x, w0.y));
            __half2 p1 = __float22half2_rn(make_float2(w0.z, w0.w));
            __half2 p2 = __float22half2_rn(make_float2(w1.x, w1.y));
            __half2 p3 = __float22half2_rn(make_float2(w1.z, w1.w));
            uint4 u;
            u.x = *(unsigned*)&p0; u.y = *(unsigned*)&p1; u.z = *(unsigned*)&p2; u.w = *(unsigned*)&p3;
            *(uint4*)&Bs[brow * S1 + bkq] = u;
        }
        __syncthreads();
        #pragma unroll
        for (int ks = 0; ks < 32; ks += 16) {
            unsigned bf[4][2];
            #pragma unroll
            for (int j = 0; j < 4; j++) {
                bf[j][0] = *(unsigned*)&Bs[(wn + 8 * j + g) * S1 + ks + 2 * t];
                bf[j][1] = *(unsigned*)&Bs[(wn + 8 * j + g) * S1 + ks + 2 * t + 8];
            }
            #pragma unroll
            for (int i = 0; i < 2; i++) {
                unsigned af[4];
                af[0] = *(unsigned*)&As[(wm + 16 * i + g) * S1 + ks + 2 * t];
                af[1] = *(unsigned*)&As[(wm + 16 * i + 8 + g) * S1 + ks + 2 * t];
                af[2] = *(unsigned*)&As[(wm + 16 * i + g) * S1 + ks + 2 * t + 8];
                af[3] = *(unsigned*)&As[(wm + 16 * i + 8 + g) * S1 + ks + 2 * t + 8];
                #pragma unroll
                for (int j = 0; j < 4; j++) mma_f16(acc[i][j], af, bf[j]);
            }
        }
        __syncthreads();
    }
    #pragma unroll
    for (int i = 0; i < 2; i++) {
        int r0 = m0 + wm + 16 * i + g;
        int r1 = r0 + 8;
        #pragma unroll
        for (int j = 0; j < 4; j++) {
            int col = wn + 8 * j + 2 * t;
            float b0v = s_b2[col], b1v = s_b2[col + 1];
            if (r0 < NN)
                *(float2*)&out[r0 * NC + col] = make_float2(acc[i][j][0] + b0v, acc[i][j][1] + b1v);
            if (r1 < NN)
                *(float2*)&out[r1 * NC + col] = make_float2(acc[i][j][2] + b0v, acc[i][j][3] + b1v);
        }
    }
}

// ---------------- host launch ----------------
extern "C" void kernel_launch(void* const* d_in, const int* in_sizes, int n_in,
                              void* d_out, int out_size) {
    const float* feat   = (const float*)d_in[0];
    const int*   src    = (const int*)d_in[1];
    const int*   dst    = (const int*)d_in[2];
    const float* nrm    = (const float*)d_in[3];
    const float* fc1_w  = (const float*)d_in[4];
    const float* fc1_b  = (const float*)d_in[5];
    const float* gamma  = (const float*)d_in[6];
    const float* beta   = (const float*)d_in[7];
    const float* fc2_w  = (const float*)d_in[8];
    const float* fc2_b  = (const float*)d_in[9];
    float* out = (float*)d_out;

    // CSR build
    k_zero<<<256, 256>>>();
    k_hist<<<(NE + 255) / 256, 256>>>(dst);
    k_scan1<<<SCAN_BLOCKS, 1024>>>();
    k_scan2<<<1, 128>>>();
    k_scan3<<<(NN + 255) / 256, 256>>>();
    k_scatter<<<(NE + 255) / 256, 256>>>(src, dst, nrm);

    // feat -> fp16, then 3 hops: fh1 -> fh0 -> fh1 -> fh0
    k_cvt<<<(NN * FD / 2 + 255) / 256, 256>>>(feat);
    int prop_blocks = (NN * 32 + 255) / 256;
    k_prop<<<prop_blocks, 256>>>(0);
    k_prop<<<prop_blocks, 256>>>(1);
    k_prop<<<prop_blocks, 256>>>(0);

    // MLP (fp16 tensor-core GEMMs; BN stats fused into GEMM1)
    dim3 g1((NN + 127) / 128, NH / 128);
    k_gemm1<<<g1, 256>>>(fc1_w, fc1_b);
    k_bnfinal<<<2, 256>>>(gamma, beta);
    k_gemm2<<<(NN + 127) / 128, 256>>>(fc2_w, fc2_b, out);
}

// round 4
// speedup vs baseline: 2.3925x; 1.0761x over previous
#include <cuda_runtime.h>
#include <cuda_fp16.h>

#define NN 100000
#define NE 1600000
#define FD 128
#define NH 512
#define NC 64
#define SCAN_BLOCKS 98   // ceil(100000/1024)

// ---------------- device scratch ----------------
__device__ int    g_deg[NN + 1];
__device__ int    g_incl[NN];
__device__ int    g_blktot[128];
__device__ int    g_rowptr[NN + 1];
__device__ int    g_cursor[NN];
__device__ int2   g_edge[NE];       // (src, wgt bits) interleaved
__device__ __half g_fh0[NN * FD];
__device__ __half g_fh1[NN * FD];
__device__ __half g_hh[NN * NH];
__device__ __half g_w1h[NH * FD];   // fc1_w as fp16
__device__ __half g_w2h[NC * NH];   // fc2_w as fp16
__device__ float  g_colsum[NH];
__device__ float  g_colsq[NH];
__device__ float  g_scale[NH];
__device__ float  g_shift[NH];

// ---------------- fp16 mma helper (m16n8k16, fp32 accum) ----------------
__device__ __forceinline__ void mma_f16(float* c, const unsigned* a, const unsigned* b) {
    asm volatile(
        "mma.sync.aligned.m16n8k16.row.col.f32.f16.f16.f32 "
        "{%0,%1,%2,%3}, {%4,%5,%6,%7}, {%8,%9}, {%0,%1,%2,%3};"
        : "+f"(c[0]), "+f"(c[1]), "+f"(c[2]), "+f"(c[3])
        : "r"(a[0]), "r"(a[1]), "r"(a[2]), "r"(a[3]), "r"(b[0]), "r"(b[1]));
}

// ---------------- cvt + zero: feat->fp16, weights->fp16, zero counters ----------------
__global__ void k_cvt(const float* __restrict__ feat,
                      const float* __restrict__ w1,
                      const float* __restrict__ w2) {
    int i = blockIdx.x * blockDim.x + threadIdx.x;
    if (i < NN * FD / 2) {
        float2 v = ((const float2*)feat)[i];
        ((__half2*)g_fh1)[i] = __float22half2_rn(v);
    }
    if (i < NH * FD / 2) {
        float2 v = ((const float2*)w1)[i];
        ((__half2*)g_w1h)[i] = __float22half2_rn(v);
    }
    if (i < NC * NH / 2) {
        float2 v = ((const float2*)w2)[i];
        ((__half2*)g_w2h)[i] = __float22half2_rn(v);
    }
    if (i < NN + 1) g_deg[i] = 0;
    if (i < NH) { g_colsum[i] = 0.f; g_colsq[i] = 0.f; }
}

// ---------------- CSR build ----------------
__global__ void k_hist(const int* __restrict__ dst) {
    int e = blockIdx.x * blockDim.x + threadIdx.x;
    if (e < NE) atomicAdd(&g_deg[dst[e]], 1);
}

__global__ void k_scan1() {
    __shared__ int sh[1024];
    int i = blockIdx.x * 1024 + threadIdx.x;
    int v = (i < NN) ? g_deg[i] : 0;
    sh[threadIdx.x] = v;
    __syncthreads();
    #pragma unroll
    for (int off = 1; off < 1024; off <<= 1) {
        int t = (threadIdx.x >= off) ? sh[threadIdx.x - off] : 0;
        __syncthreads();
        sh[threadIdx.x] += t;
        __syncthreads();
    }
    if (i < NN) g_incl[i] = sh[threadIdx.x];
    if (threadIdx.x == 1023) g_blktot[blockIdx.x] = sh[1023];
}

// merged scan2+scan3: every block redundantly scans the 98 block totals
__global__ void k_scan23() {
    __shared__ int sh[128];
    if (threadIdx.x < 128)
        sh[threadIdx.x] = (threadIdx.x < SCAN_BLOCKS) ? g_blktot[threadIdx.x] : 0;
    __syncthreads();
    #pragma unroll
    for (int off = 1; off < 128; off <<= 1) {
        int t = 0;
        if (threadIdx.x < 128 && threadIdx.x >= off) t = sh[threadIdx.x - off];
        __syncthreads();
        if (threadIdx.x < 128) sh[threadIdx.x] += t;
        __syncthreads();
    }
    int base = (blockIdx.x == 0) ? 0 : sh[blockIdx.x - 1];
    int i = blockIdx.x * 1024 + threadIdx.x;
    if (i < NN) {
        int excl = g_incl[i] - g_deg[i] + base;
        g_rowptr[i] = excl;
        g_cursor[i] = excl;
        if (i == NN - 1) g_rowptr[NN] = g_incl[i] + base;
    }
}

__global__ void k_scatter(const int* __restrict__ src, const int* __restrict__ dst,
                          const float* __restrict__ nrm) {
    int e = blockIdx.x * blockDim.x + threadIdx.x;
    if (e < NE) {
        int d = dst[e];
        int pos = atomicAdd(&g_cursor[d], 1);
        g_edge[pos] = make_int2(src[e], __float_as_int(nrm[e]));
    }
}

// ---------------- K-hop propagation: warp per dst, fp16 rows, fp32 accumulate ----------------
__global__ void k_prop(int par) {
    int gt = blockIdx.x * blockDim.x + threadIdx.x;
    int node = gt >> 5;
    int lane = gt & 31;
    if (node >= NN) return;
    const uint2* in2  = (const uint2*)(par ? g_fh0 : g_fh1);
    uint2*       out2 = (uint2*)(par ? g_fh1 : g_fh0);
    int beg = g_rowptr[node];
    int end = g_rowptr[node + 1];
    float4 acc = make_float4(0.f, 0.f, 0.f, 0.f);
    int j = beg;
    for (; j + 2 <= end; j += 2) {
        int2 e0 = g_edge[j];
        int2 e1 = g_edge[j + 1];
        uint2 v0 = in2[(long)e0.x * 32 + lane];
        uint2 v1 = in2[(long)e1.x * 32 + lane];
        float w0 = __int_as_float(e0.y), w1 = __int_as_float(e1.y);
        float2 a0 = __half22float2(*(__half2*)&v0.x);
        float2 a1 = __half22float2(*(__half2*)&v0.y);
        float2 b0 = __half22float2(*(__half2*)&v1.x);
        float2 b1 = __half22float2(*(__half2*)&v1.y);
        acc.x = fmaf(a0.x, w0, fmaf(b0.x, w1, acc.x));
        acc.y = fmaf(a0.y, w0, fmaf(b0.y, w1, acc.y));
        acc.z = fmaf(a1.x, w0, fmaf(b1.x, w1, acc.z));
        acc.w = fmaf(a1.y, w0, fmaf(b1.y, w1, acc.w));
    }
    if (j < end) {
        int2 e0 = g_edge[j];
        uint2 v0 = in2[(long)e0.x * 32 + lane];
        float w0 = __int_as_float(e0.y);
        float2 a0 = __half22float2(*(__half2*)&v0.x);
        float2 a1 = __half22float2(*(__half2*)&v0.y);
        acc.x = fmaf(a0.x, w0, acc.x);
        acc.y = fmaf(a0.y, w0, acc.y);
        acc.z = fmaf(a1.x, w0, acc.z);
        acc.w = fmaf(a1.y, w0, acc.w);
    }
    uint2 o;
    *(__half2*)&o.x = __float22half2_rn(make_float2(acc.x, acc.y));
    *(__half2*)&o.y = __float22half2_rn(make_float2(acc.z, acc.w));
    out2[node * 32 + lane] = o;
}

// ---------------- GEMM1 (fp16 MMA, reg double-buffered): h = ft @ W1^T + b1 + BN stats ----------------
#define S1 40   // smem stride in halves -> conflict-free fragment loads
__global__ __launch_bounds__(256) void k_gemm1(const float* __restrict__ bias) {
    __shared__ __half As[128 * S1];
    __shared__ __half Bs[128 * S1];
    __shared__ float s_bias[128];
    const int tid = threadIdx.x;
    const int m0 = blockIdx.x * 128, n0 = blockIdx.y * 128;
    const int wid = tid >> 5, lane = tid & 31;
    const int g = lane >> 2, t = lane & 3;
    const int wm = (wid & 1) * 64, wn = (wid >> 1) * 32;
    if (tid < 128) s_bias[tid] = bias[n0 + tid];

    float acc[4][4][4];
    #pragma unroll
    for (int i = 0; i < 4; i++)
        #pragma unroll
        for (int j = 0; j < 4; j++)
            #pragma unroll
            for (int r = 0; r < 4; r++) acc[i][j][r] = 0.f;

    const int lrow = tid >> 1, lkq = (tid & 1) * 16;
    int gr = m0 + lrow; if (gr >= NN) gr = NN - 1;
    const __half* aptr = &g_fh0[gr * FD + lkq];
    const __half* bptr = &g_w1h[(n0 + lrow) * FD + lkq];

    uint4 ra0 = *(const uint4*)(aptr);
    uint4 ra1 = *(const uint4*)(aptr + 8);
    uint4 rb0 = *(const uint4*)(bptr);
    uint4 rb1 = *(const uint4*)(bptr + 8);
    *(uint4*)&As[lrow * S1 + lkq]     = ra0;
    *(uint4*)&As[lrow * S1 + lkq + 8] = ra1;
    *(uint4*)&Bs[lrow * S1 + lkq]     = rb0;
    *(uint4*)&Bs[lrow * S1 + lkq + 8] = rb1;
    __syncthreads();

    for (int kt = 0; kt < FD; kt += 32) {
        bool more = (kt + 32 < FD);
        if (more) {
            ra0 = *(const uint4*)(aptr + kt + 32);
            ra1 = *(const uint4*)(aptr + kt + 40);
            rb0 = *(const uint4*)(bptr + kt + 32);
            rb1 = *(const uint4*)(bptr + kt + 40);
        }
        #pragma unroll
        for (int ks = 0; ks < 32; ks += 16) {
            unsigned bf[4][2];
            #pragma unroll
            for (int j = 0; j < 4; j++) {
                bf[j][0] = *(unsigned*)&Bs[(wn + 8 * j + g) * S1 + ks + 2 * t];
                bf[j][1] = *(unsigned*)&Bs[(wn + 8 * j + g) * S1 + ks + 2 * t + 8];
            }
            #pragma unroll
            for (int i = 0; i < 4; i++) {
                unsigned af[4];
                af[0] = *(unsigned*)&As[(wm + 16 * i + g) * S1 + ks + 2 * t];
                af[1] = *(unsigned*)&As[(wm + 16 * i + 8 + g) * S1 + ks + 2 * t];
                af[2] = *(unsigned*)&As[(wm + 16 * i + g) * S1 + ks + 2 * t + 8];
                af[3] = *(unsigned*)&As[(wm + 16 * i + 8 + g) * S1 + ks + 2 * t + 8];
                #pragma unroll
                for (int j = 0; j < 4; j++) mma_f16(acc[i][j], af, bf[j]);
            }
        }
        __syncthreads();
        if (more) {
            *(uint4*)&As[lrow * S1 + lkq]     = ra0;
            *(uint4*)&As[lrow * S1 + lkq + 8] = ra1;
            *(uint4*)&Bs[lrow * S1 + lkq]     = rb0;
            *(uint4*)&Bs[lrow * S1 + lkq + 8] = rb1;
            __syncthreads();
        }
    }

    // Epilogue: bias, write h (fp16), fused BN partials
    float s0[4] = {0.f,0.f,0.f,0.f}, q0[4] = {0.f,0.f,0.f,0.f};
    float s1[4] = {0.f,0.f,0.f,0.f}, q1[4] = {0.f,0.f,0.f,0.f};
    #pragma unroll
    for (int i = 0; i < 4; i++) {
        int r0 = m0 + wm + 16 * i + g;
        int r1 = r0 + 8;
        #pragma unroll
        for (int j = 0; j < 4; j++) {
            int lc = wn + 8 * j + 2 * t;
            float b0v = s_bias[lc], b1v = s_bias[lc + 1];
            float h00 = acc[i][j][0] + b0v, h01 = acc[i][j][1] + b1v;
            float h10 = acc[i][j][2] + b0v, h11 = acc[i][j][3] + b1v;
            if (r0 < NN) {
                *(__half2*)&g_hh[r0 * NH + n0 + lc] = __float22half2_rn(make_float2(h00, h01));
                s0[j] += h00; q0[j] = fmaf(h00, h00, q0[j]);
                s1[j] += h01; q1[j] = fmaf(h01, h01, q1[j]);
            }
            if (r1 < NN) {
                *(__half2*)&g_hh[r1 * NH + n0 + lc] = __float22half2_rn(make_float2(h10, h11));
                s0[j] += h10; q0[j] = fmaf(h10, h10, q0[j]);
                s1[j] += h11; q1[j] = fmaf(h11, h11, q1[j]);
            }
        }
    }
    #pragma unroll
    for (int j = 0; j < 4; j++) {
        #pragma unroll
        for (int off = 4; off < 32; off <<= 1) {
            s0[j] += __shfl_xor_sync(0xffffffff, s0[j], off);
            q0[j] += __shfl_xor_sync(0xffffffff, q0[j], off);
            s1[j] += __shfl_xor_sync(0xffffffff, s1[j], off);
            q1[j] += __shfl_xor_sync(0xffffffff, q1[j], off);
        }
    }
    if (lane < 4) {
        #pragma unroll
        for (int j = 0; j < 4; j++) {
            int col = n0 + wn + 8 * j + 2 * lane;
            atomicAdd(&g_colsum[col],     s0[j]);
            atomicAdd(&g_colsum[col + 1], s1[j]);
            atomicAdd(&g_colsq[col],      q0[j]);
            atomicAdd(&g_colsq[col + 1],  q1[j]);
        }
    }
}

__global__ void k_bnfinal(const float* __restrict__ gamma, const float* __restrict__ beta) {
    int c = blockIdx.x * blockDim.x + threadIdx.x;
    if (c < NH) {
        float mean = g_colsum[c] * (1.0f / NN);
        float var  = g_colsq[c] * (1.0f / NN) - mean * mean;
        float sc = gamma[c] * rsqrtf(var + 1e-5f);
        g_scale[c] = sc;
        g_shift[c] = beta[c] - mean * sc;
    }
}

// ---------------- GEMM2 (fp16 MMA, reg double-buffered): out = relu(h*sc+sh) @ W2^T + b2 ----------------
__global__ __launch_bounds__(256) void k_gemm2(const float* __restrict__ b2,
                                               float* __restrict__ out) {
    __shared__ __half As[128 * S1];
    __shared__ __half Bs[64 * S1];
    __shared__ float s_scale[NH];
    __shared__ float s_shift[NH];
    __shared__ float s_b2[NC];
    const int tid = threadIdx.x;
    const int m0 = blockIdx.x * 128;
    const int wid = tid >> 5, lane = tid & 31;
    const int g = lane >> 2, t = lane & 3;
    const int wm = (wid & 3) * 32, wn = (wid >> 2) * 32;
    for (int i = tid; i < NH; i += 256) { s_scale[i] = g_scale[i]; s_shift[i] = g_shift[i]; }
    if (tid < NC) s_b2[tid] = b2[tid];

    float acc[2][4][4];
    #pragma unroll
    for (int i = 0; i < 2; i++)
        #pragma unroll
        for (int j = 0; j < 4; j++)
            #pragma unroll
            for (int r = 0; r < 4; r++) acc[i][j][r] = 0.f;

    const int lrow = tid >> 1, lkq = (tid & 1) * 16;
    const int brow = tid >> 2, bkq = (tid & 3) * 8;
    int gr = m0 + lrow; if (gr >= NN) gr = NN - 1;
    const __half* aptr = &g_hh[gr * NH + lkq];
    const __half* bptr = &g_w2h[brow * NH + bkq];

    uint4 ra0 = *(const uint4*)(aptr);
    uint4 ra1 = *(const uint4*)(aptr + 8);
    uint4 rb0 = *(const uint4*)(bptr);
    __syncthreads();   // s_scale/s_shift ready

    // transform+store helper expanded inline (k-base needed)
    {
        unsigned res[8];
        const unsigned* vp = (const unsigned*)&ra0;
        #pragma unroll
        for (int p = 0; p < 4; p++) {
            int k = lkq + p * 2;
            float2 f = __half22float2(*(__half2*)&vp[p]);
            f.x = fmaxf(fmaf(f.x, s_scale[k],     s_shift[k]),     0.f);
            f.y = fmaxf(fmaf(f.y, s_scale[k + 1], s_shift[k + 1]), 0.f);
            __half2 h = __float22half2_rn(f);
            res[p] = *(unsigned*)&h;
        }
        const unsigned* wq = (const unsigned*)&ra1;
        #pragma unroll
        for (int p = 0; p < 4; p++) {
            int k = lkq + 8 + p * 2;
            float2 f = __half22float2(*(__half2*)&wq[p]);
            f.x = fmaxf(fmaf(f.x, s_scale[k],     s_shift[k]),     0.f);
            f.y = fmaxf(fmaf(f.y, s_scale[k + 1], s_shift[k + 1]), 0.f);
            __half2 h = __float22half2_rn(f);
            res[p + 4] = *(unsigned*)&h;
        }
        *(uint4*)&As[lrow * S1 + lkq]     = *(uint4*)&res[0];
        *(uint4*)&As[lrow * S1 + lkq + 8] = *(uint4*)&res[4];
        *(uint4*)&Bs[brow * S1 + bkq] = rb0;
    }
    __syncthreads();

    for (int kt = 0; kt < NH; kt += 32) {
        bool more = (kt + 32 < NH);
        if (more) {
            ra0 = *(const uint4*)(aptr + kt + 32);
            ra1 = *(const uint4*)(aptr + kt + 40);
            rb0 = *(const uint4*)(bptr + kt + 32);
        }
        #pragma unroll
        for (int ks = 0; ks < 32; ks += 16) {
            unsigned bf[4][2];
            #pragma unroll
            for (int j = 0; j < 4; j++) {
                bf[j][0] = *(unsigned*)&Bs[(wn + 8 * j + g) * S1 + ks + 2 * t];
                bf[j][1] = *(unsigned*)&Bs[(wn + 8 * j + g) * S1 + ks + 2 * t + 8];
            }
            #pragma unroll
            for (int i = 0; i < 2; i++) {
                unsigned af[4];
                af[0] = *(unsigned*)&As[(wm + 16 * i + g) * S1 + ks + 2 * t];
                af[1] = *(unsigned*)&As[(wm + 16 * i + 8 + g) * S1 + ks + 2 * t];
                af[2] = *(unsigned*)&As[(wm + 16 * i + g) * S1 + ks + 2 * t + 8];
                af[3] = *(unsigned*)&As[(wm + 16 * i + 8 + g) * S1 + ks + 2 * t + 8];
                #pragma unroll
                for (int j = 0; j < 4; j++) mma_f16(acc[i][j], af, bf[j]);
            }
        }
        __syncthreads();
        if (more) {
            int kb = kt + 32;
            unsigned res[8];
            const unsigned* vp = (const unsigned*)&ra0;
            #pragma unroll
            for (int p = 0; p < 4; p++) {
                int k = kb + lkq + p * 2;
                float2 f = __half22float2(*(__half2*)&vp[p]);
                f.x = fmaxf(fmaf(f.x, s_scale[k],     s_shift[k]),     0.f);
                f.y = fmaxf(fmaf(f.y, s_scale[k + 1], s_shift[k + 1]), 0.f);
                __half2 h = __float22half2_rn(f);
                res[p] = *(unsigned*)&h;
            }
            const unsigned* wq = (const unsigned*)&ra1;
            #pragma unroll
            for (int p = 0; p < 4; p++) {
                int k = kb + lkq + 8 + p * 2;
                float2 f = __half22float2(*(__half2*)&wq[p]);
                f.x = fmaxf(fmaf(f.x, s_scale[k],     s_shift[k]),     0.f);
                f.y = fmaxf(fmaf(f.y, s_scale[k + 1], s_shift[k + 1]), 0.f);
                __half2 h = __float22half2_rn(f);
                res[p + 4] = *(unsigned*)&h;
            }
            *(uint4*)&As[lrow * S1 + lkq]     = *(uint4*)&res[0];
            *(uint4*)&As[lrow * S1 + lkq + 8] = *(uint4*)&res[4];
            *(uint4*)&Bs[brow * S1 + bkq] = rb0;
            __syncthreads();
        }
    }
    #pragma unroll
    for (int i = 0; i < 2; i++) {
        int r0 = m0 + wm + 16 * i + g;
        int r1 = r0 + 8;
        #pragma unroll
        for (int j = 0; j < 4; j++) {
            int col = wn + 8 * j + 2 * t;
            float b0v = s_b2[col], b1v = s_b2[col + 1];
            if (r0 < NN)
                *(float2*)&out[r0 * NC + col] = make_float2(acc[i][j][0] + b0v, acc[i][j][1] + b1v);
            if (r1 < NN)
                *(float2*)&out[r1 * NC + col] = make_float2(acc[i][j][2] + b0v, acc[i][j][3] + b1v);
        }
    }
}

// ---------------- host launch ----------------
extern "C" void kernel_launch(void* const* d_in, const int* in_sizes, int n_in,
                              void* d_out, int out_size) {
    const float* feat   = (const float*)d_in[0];
    const int*   src    = (const int*)d_in[1];
    const int*   dst    = (const int*)d_in[2];
    const float* nrm    = (const float*)d_in[3];
    const float* fc1_w  = (const float*)d_in[4];
    const float* fc1_b  = (const float*)d_in[5];
    const float* gamma  = (const float*)d_in[6];
    const float* beta   = (const float*)d_in[7];
    const float* fc2_w  = (const float*)d_in[8];
    const float* fc2_b  = (const float*)d_in[9];
    float* out = (float*)d_out;

    // cvt (feat+weights) + zero counters, then CSR build
    k_cvt<<<(NN * FD / 2 + 255) / 256, 256>>>(feat, fc1_w, fc2_w);
    k_hist<<<(NE + 255) / 256, 256>>>(dst);
    k_scan1<<<SCAN_BLOCKS, 1024>>>();
    k_scan23<<<SCAN_BLOCKS, 1024>>>();
    k_scatter<<<(NE + 255) / 256, 256>>>(src, dst, nrm);

    // 3 hops: fh1 -> fh0 -> fh1 -> fh0
    int prop_blocks = (NN * 32 + 255) / 256;
    k_prop<<<prop_blocks, 256>>>(0);
    k_prop<<<prop_blocks, 256>>>(1);
    k_prop<<<prop_blocks, 256>>>(0);

    // MLP
    dim3 g1((NN + 127) / 128, NH / 128);
    k_gemm1<<<g1, 256>>>(fc1_b);
    k_bnfinal<<<2, 256>>>(gamma, beta);
    k_gemm2<<<(NN + 127) / 128, 256>>>(fc2_b, out);
}